// round 7
// baseline (speedup 1.0000x reference)
#include <cuda_runtime.h>

// QuantumConvLayer: out[:,2i]   = cos(q[2i]) * cos(pi*x[:,2i])
//                   out[:,2i+1] = out[:,2i]  * cos(q[2i+1] + pi*x[:,2i+1])
// Streaming HBM-bound: 256MB read + 256MB write, zero reuse.
// R7: persistent single-wave grid (148 SMs x 8 CTAs = 1184 blocks), each
// block grid-strides over 1024-float4 tiles. Removes ~13 wave transitions
// and tail imbalance; q/cos(q) hoisted (phase is loop-invariant). Inner
// loop: 4 coalesced LDG.128 (MLP=4) -> MUFU -> 4 STG.128, all streaming.

#ifndef QC_PI
#define QC_PI 3.14159265358979323846f
#endif

#define VPT 4    // float4s per thread per tile
#define TPB 256  // threads per block
#define TILE (TPB * VPT)          // 1024 float4s per tile
#define NBLK 1184                 // 148 SMs * 8 resident CTAs -> one wave

__global__ void __launch_bounds__(TPB)
qconv_kernel(const float4* __restrict__ x4,
             const float*  __restrict__ q,
             float4* __restrict__ out4,
             int n_tiles)
{
    // tile stride (1024) and block base are 0 mod 4 -> q phase = tid & 3,
    // invariant across the whole loop. Hoist q and cos(q).
    const float4* q4 = (const float4*)q;
    float4 qa = __ldg(q4 + (threadIdx.x & 3));
    float ce = __cosf(qa.x);   // cos(q[c])
    float cf = __cosf(qa.z);   // cos(q[c+2])

    for (int tile = blockIdx.x; tile < n_tiles; tile += NBLK) {
        int base = tile * TILE + threadIdx.x;

        float4 v0 = __ldcs(x4 + base + 0 * TPB);
        float4 v1 = __ldcs(x4 + base + 1 * TPB);
        float4 v2 = __ldcs(x4 + base + 2 * TPB);
        float4 v3 = __ldcs(x4 + base + 3 * TPB);

        float a0 = ce * __cosf(QC_PI * v0.x);
        float b0 = a0 * __cosf(fmaf(QC_PI, v0.y, qa.y));
        float a1 = cf * __cosf(QC_PI * v0.z);
        float b1 = a1 * __cosf(fmaf(QC_PI, v0.w, qa.w));
        __stcs(out4 + base + 0 * TPB, make_float4(a0, b0, a1, b1));

        float a2 = ce * __cosf(QC_PI * v1.x);
        float b2 = a2 * __cosf(fmaf(QC_PI, v1.y, qa.y));
        float a3 = cf * __cosf(QC_PI * v1.z);
        float b3 = a3 * __cosf(fmaf(QC_PI, v1.w, qa.w));
        __stcs(out4 + base + 1 * TPB, make_float4(a2, b2, a3, b3));

        float a4 = ce * __cosf(QC_PI * v2.x);
        float b4 = a4 * __cosf(fmaf(QC_PI, v2.y, qa.y));
        float a5 = cf * __cosf(QC_PI * v2.z);
        float b5 = a5 * __cosf(fmaf(QC_PI, v2.w, qa.w));
        __stcs(out4 + base + 2 * TPB, make_float4(a4, b4, a5, b5));

        float a6 = ce * __cosf(QC_PI * v3.x);
        float b6 = a6 * __cosf(fmaf(QC_PI, v3.y, qa.y));
        float a7 = cf * __cosf(QC_PI * v3.z);
        float b7 = a7 * __cosf(fmaf(QC_PI, v3.w, qa.w));
        __stcs(out4 + base + 3 * TPB, make_float4(a6, b6, a7, b7));
    }
}

extern "C" void kernel_launch(void* const* d_in, const int* in_sizes, int n_in,
                              void* d_out, int out_size)
{
    const float4* x4 = (const float4*)d_in[0];
    const float*  q  = (const float*)d_in[1];
    float4* out4     = (float4*)d_out;

    int n_elems = in_sizes[0];        // B * 16 = 67108864
    int n4 = n_elems >> 2;            // 16777216 float4s (divisible by TILE)
    int n_tiles = n4 / TILE;          // 16384 tiles

    qconv_kernel<<<NBLK, TPB>>>(x4, q, out4, n_tiles);
}

// round 8
// speedup vs baseline: 1.1339x; 1.1339x over previous
#include <cuda_runtime.h>

// QuantumConvLayer: out[:,2i]   = cos(q[2i]) * cos(pi*x[:,2i])
//                   out[:,2i+1] = out[:,2i]  * cos(q[2i+1] + pi*x[:,2i+1])
// Streaming HBM-bound: 256MB read + 256MB write, zero reuse.
// R8: R4-family (the measured-best memory shape: VPT=4 block-strided,
// fully coalesced, MLP=4 front-batched, multi-wave launch) with TPB=512:
// 2048-float4 contiguous tile per block (longer same-direction bursts),
// exact grid (8192 blocks, zero predicates), single q float4 per thread.
// Persistent/grid-stride rejected (R7: loop-carried reg reuse serializes
// loads); VPT=8 rejected (R5: occupancy loss beats in-flight gain).

#ifndef QC_PI
#define QC_PI 3.14159265358979323846f
#endif

#define VPT 4    // float4s per thread
#define TPB 512  // threads per block
#define TILE (TPB * VPT)   // 2048 float4s per block

__global__ void __launch_bounds__(TPB)
qconv_kernel(const float4* __restrict__ x4,
             const float*  __restrict__ q,
             float4* __restrict__ out4)
{
    int base = blockIdx.x * TILE + threadIdx.x;

    // 4 coalesced 128-bit streaming loads, front-batched (MLP=4)
    float4 v0 = __ldcs(x4 + base + 0 * TPB);
    float4 v1 = __ldcs(x4 + base + 1 * TPB);
    float4 v2 = __ldcs(x4 + base + 2 * TPB);
    float4 v3 = __ldcs(x4 + base + 3 * TPB);

    // stride TPB=512 is 0 mod 4 -> all 4 elements share row phase (base & 3)
    const float4* q4 = (const float4*)q;
    float4 qa = __ldg(q4 + (base & 3));   // q[c..c+3], c = 4*(base&3)

    float ce = __cosf(qa.x);   // cos(q[c])
    float cf = __cosf(qa.z);   // cos(q[c+2])

    {
        float a0 = ce * __cosf(QC_PI * v0.x);
        float b0 = a0 * __cosf(fmaf(QC_PI, v0.y, qa.y));
        float a1 = cf * __cosf(QC_PI * v0.z);
        float b1 = a1 * __cosf(fmaf(QC_PI, v0.w, qa.w));
        __stcs(out4 + base + 0 * TPB, make_float4(a0, b0, a1, b1));
    }
    {
        float a0 = ce * __cosf(QC_PI * v1.x);
        float b0 = a0 * __cosf(fmaf(QC_PI, v1.y, qa.y));
        float a1 = cf * __cosf(QC_PI * v1.z);
        float b1 = a1 * __cosf(fmaf(QC_PI, v1.w, qa.w));
        __stcs(out4 + base + 1 * TPB, make_float4(a0, b0, a1, b1));
    }
    {
        float a0 = ce * __cosf(QC_PI * v2.x);
        float b0 = a0 * __cosf(fmaf(QC_PI, v2.y, qa.y));
        float a1 = cf * __cosf(QC_PI * v2.z);
        float b1 = a1 * __cosf(fmaf(QC_PI, v2.w, qa.w));
        __stcs(out4 + base + 2 * TPB, make_float4(a0, b0, a1, b1));
    }
    {
        float a0 = ce * __cosf(QC_PI * v3.x);
        float b0 = a0 * __cosf(fmaf(QC_PI, v3.y, qa.y));
        float a1 = cf * __cosf(QC_PI * v3.z);
        float b1 = a1 * __cosf(fmaf(QC_PI, v3.w, qa.w));
        __stcs(out4 + base + 3 * TPB, make_float4(a0, b0, a1, b1));
    }
}

extern "C" void kernel_launch(void* const* d_in, const int* in_sizes, int n_in,
                              void* d_out, int out_size)
{
    const float4* x4 = (const float4*)d_in[0];
    const float*  q  = (const float*)d_in[1];
    float4* out4     = (float4*)d_out;

    int n_elems = in_sizes[0];   // B * 16 = 67108864
    int n4 = n_elems >> 2;       // 16777216 float4s; divisible by TILE=2048

    int blocks = n4 / TILE;      // 8192, exact
    qconv_kernel<<<blocks, TPB>>>(x4, q, out4);
}